// round 15
// baseline (speedup 1.0000x reference)
#include <cuda_runtime.h>
#include <cuda_fp16.h>
#include <stdint.h>

// ---------------- problem constants ----------------
namespace {
constexpr int T_  = 4096;
constexpr int D_  = 1024;
constexpr int E_  = 8;
constexpr int F_  = 2816;
constexpr int NP  = T_ * 2;       // 8192 (token,k) pairs
constexpr int N1  = 2 * F_;       // 5632
constexpr int BM  = 128;
constexpr int MAXTILES = 72;

// smem per k64-chunk buffer: 2 planes (Ah, Bh) of 128x64 fp16 = 16KB each
constexpr int PL   = 16384;
constexpr int BUF  = 2 * PL;          // 32768 per buffer
constexpr int NBUF = 3;
constexpr int SMEM_DYN = NBUF * BUF;  // 98304 (>= G2 staging 67584)

// prep region sizes (float4 units)
constexpr int N4_X   = T_ * D_ / 4;
constexpr int N4_GUP = (int)((size_t)E_ * N1 * D_ / 4);
constexpr int N4_DWN = (int)((size_t)E_ * D_ * F_ / 4);
constexpr int N4_OUT = T_ * D_ / 4;
constexpr int N4_TOTAL = N4_X + N4_GUP + N4_DWN + N4_OUT;
}

// ---------------- device scratch ----------------
__device__ __align__(16) __half g_x_hi[(size_t)T_ * D_];
__device__ __align__(16) __half g_gup_hi[(size_t)E_ * N1 * D_];
__device__ __align__(16) __half g_dwn_hi[(size_t)E_ * D_ * F_];
__device__ __align__(16) __half g_act_hi[(size_t)NP * F_];

__device__ int g_rowtok[NP];
__device__ int g_rowpair[NP];
__device__ int g_tile_e[MAXTILES];
__device__ int g_tile_r0[MAXTILES];
__device__ int g_tile_rows[MAXTILES];
__device__ int g_ntiles;

// ---------------- helpers ----------------
__device__ __forceinline__ uint32_t smem_u32(const void* p) {
    uint32_t a;
    asm("{ .reg .u64 t; cvta.to.shared.u64 t, %1; cvt.u32.u64 %0, t; }" : "=r"(a) : "l"(p));
    return a;
}
// SW128 swizzle: tile row r (0..127) = one 128B smem row; 16B unit q (0..7)
__device__ __forceinline__ uint32_t sw(int r, int q) {
    return (uint32_t)((r << 7) | (((q ^ (r & 7))) << 4));
}
__device__ __forceinline__ void hi4h(float4 v, uint32_t& h0, uint32_t& h1) {
    __half2 H0 = __floats2half2_rn(v.x, v.y);
    __half2 H1 = __floats2half2_rn(v.z, v.w);
    h0 = *(uint32_t*)&H0; h1 = *(uint32_t*)&H1;
}
__device__ __forceinline__ void ldsm4(uint32_t& r0, uint32_t& r1, uint32_t& r2, uint32_t& r3,
                                      uint32_t addr) {
    asm volatile("ldmatrix.sync.aligned.m8n8.x4.shared.b16 {%0,%1,%2,%3}, [%4];"
                 : "=r"(r0), "=r"(r1), "=r"(r2), "=r"(r3) : "r"(addr));
}
__device__ __forceinline__ void mma16816(float* c, const uint32_t* a, uint32_t b0, uint32_t b1) {
    asm("mma.sync.aligned.m16n8k16.row.col.f32.f16.f16.f32 "
        "{%0,%1,%2,%3}, {%4,%5,%6,%7}, {%8,%9}, {%0,%1,%2,%3};"
        : "+f"(c[0]), "+f"(c[1]), "+f"(c[2]), "+f"(c[3])
        : "r"(a[0]), "r"(a[1]), "r"(a[2]), "r"(a[3]), "r"(b0), "r"(b1));
}
__device__ __forceinline__ void cp_async16(uint32_t dst, const void* src, int sz) {
    asm volatile("cp.async.cg.shared.global [%0], [%1], 16, %2;"
                 :: "r"(dst), "l"(src), "r"(sz) : "memory");
}
__device__ __forceinline__ void cp_mbar_arrive(uint32_t mbar) {
    asm volatile("cp.async.mbarrier.arrive.noinc.shared.b64 [%0];" :: "r"(mbar) : "memory");
}
__device__ __forceinline__ void mbar_init(uint32_t mbar, uint32_t cnt) {
    asm volatile("mbarrier.init.shared.b64 [%0], %1;" :: "r"(mbar), "r"(cnt) : "memory");
}
__device__ __forceinline__ void mbar_arrive(uint32_t mbar) {
    asm volatile("mbarrier.arrive.shared.b64 _, [%0];" :: "r"(mbar) : "memory");
}
__device__ __forceinline__ void mbar_wait(uint32_t mbar, uint32_t parity) {
    asm volatile(
        "{\n\t.reg .pred P;\n\t"
        "WL_%=:\n\t"
        "mbarrier.try_wait.parity.acquire.cta.shared::cta.b64 P, [%0], %1, 0x989680;\n\t"
        "@P bra.uni WD_%=;\n\t"
        "bra.uni WL_%=;\n\t"
        "WD_%=:\n\t}"
        :: "r"(mbar), "r"(parity) : "memory");
}
__device__ __forceinline__ void redadd(float* p, float v) {
    asm volatile("red.global.add.f32 [%0], %1;" :: "l"(p), "f"(v) : "memory");
}

// ---------------- merged single-block routing ----------------
__global__ void k_route(const int* __restrict__ ids) {
    __shared__ int scnt[E_];
    __shared__ int soff[E_ + 1];
    const int tid = threadIdx.x;
    if (tid < E_) scnt[tid] = 0;
    __syncthreads();

    int pe[NP / 1024], ps[NP / 1024];
#pragma unroll
    for (int t = 0; t < NP / 1024; t++) {
        int p = tid + t * 1024;
        int e = ids[p];
        e = e < 0 ? 0 : (e >= E_ ? E_ - 1 : e);
        pe[t] = e;
        ps[t] = atomicAdd(&scnt[e], 1);
    }
    __syncthreads();
    if (tid == 0) {
        int off = 0;
        soff[0] = 0;
        for (int e = 0; e < E_; e++) { off += scnt[e]; soff[e + 1] = off; }
        int nt = 0;
        for (int e = 0; e < E_; e++)
            for (int r0 = soff[e]; r0 < soff[e + 1]; r0 += BM) {
                g_tile_e[nt] = e; g_tile_r0[nt] = r0;
                int rem = soff[e + 1] - r0;
                g_tile_rows[nt] = rem < BM ? rem : BM;
                nt++;
            }
        g_ntiles = nt;
    }
    __syncthreads();
#pragma unroll
    for (int t = 0; t < NP / 1024; t++) {
        int p = tid + t * 1024;
        int gr = soff[pe[t]] + ps[t];
        g_rowtok[gr]  = p >> 1;
        g_rowpair[gr] = p;
    }
}

// ---------------- merged prep: fp32 -> fp16 casts + d_out zeroing ----------------
__global__ void k_prep(const float4* __restrict__ x, const float4* __restrict__ gup,
                       const float4* __restrict__ dwn, float4* __restrict__ out) {
    int i = blockIdx.x * 256 + threadIdx.x;
    if (i < N4_X) {
        float4 v = x[i];
        uint32_t h0, h1;
        hi4h(v, h0, h1);
        ((uint2*)g_x_hi)[i] = make_uint2(h0, h1);
        return;
    }
    i -= N4_X;
    if (i < N4_GUP) {
        float4 v = gup[i];
        uint32_t h0, h1;
        hi4h(v, h0, h1);
        ((uint2*)g_gup_hi)[i] = make_uint2(h0, h1);
        return;
    }
    i -= N4_GUP;
    if (i < N4_DWN) {
        float4 v = dwn[i];
        uint32_t h0, h1;
        hi4h(v, h0, h1);
        ((uint2*)g_dwn_hi)[i] = make_uint2(h0, h1);
        return;
    }
    i -= N4_DWN;
    if (i < N4_OUT) out[i] = make_float4(0.f, 0.f, 0.f, 0.f);
}

// ---------------- pure fp16 HMMA grouped GEMM, mbarrier pipeline ----------
// block 128x128, 8 warps (2m x 4n), warp 64x32, occ 2, BK=64, SW128 swizzle.
// NO __syncthreads in mainloop: 3-stage full/empty mbarrier ring; warps drift
// up to 3 stages. cp.async completion -> cp.async.mbarrier.arrive.noinc.
// G1: 64 j per block (128 interleaved gate/up B-rows)  KDIM=1024, NC=16
// G2: 128 n per block                                  KDIM=2816, NC=44
template <bool G1>
__global__ void __launch_bounds__(256, 2)
moe_gemm_mma(const float* __restrict__ tw, float* __restrict__ outp) {
    constexpr int KDIM = G1 ? D_ : F_;
    constexpr int NC   = KDIM / 64;   // 16 or 44, both >= 3

    const int bt = blockIdx.y;
    if (bt >= g_ntiles) return;

    const int e    = g_tile_e[bt];
    const int row0 = g_tile_r0[bt];
    const int rows = g_tile_rows[bt];
    const int bn0  = blockIdx.x * (G1 ? 64 : 128);

    const char* __restrict__ Ab = (const char*)(G1 ? g_x_hi : g_act_hi);
    const size_t eoff = (size_t)e * (G1 ? (size_t)N1 * D_ : (size_t)D_ * F_);
    const char* __restrict__ Bb = (const char*)((G1 ? g_gup_hi : g_dwn_hi) + eoff);

    extern __shared__ __align__(16) char dynraw[];
    const uint32_t dynbase = smem_u32(dynraw);

    __shared__ int   s_map[BM];
    __shared__ int   s_out[BM];
    __shared__ float s_wt[BM];
    __shared__ __align__(8) unsigned long long s_mb[2 * NBUF];  // full[0..2], empty[3..5]

    const int tid  = threadIdx.x;
    const int wid  = tid >> 5;
    const int lane = tid & 31;

    if (tid < BM) {
        int amap = -1, omap = -1;
        float w = 0.f;
        if (tid < rows) {
            if (G1) { amap = g_rowtok[row0 + tid]; omap = row0 + tid; }
            else    { amap = row0 + tid;           omap = g_rowpair[row0 + tid];
                      w = tw[omap]; }
        }
        s_map[tid] = amap; s_out[tid] = omap; s_wt[tid] = w;
    }
    if (tid == 0) {
#pragma unroll
        for (int s = 0; s < 2 * NBUF; s++) mbar_init(smem_u32(&s_mb[s]), 256);
    }
    __syncthreads();
    const uint32_t mb0 = smem_u32(&s_mb[0]);          // full[b]  = mb0 + b*8
    const uint32_t me0 = mb0 + NBUF * 8;              // empty[b] = me0 + b*8

    // ---- hoisted cp.async addressing: 4 A units + 4 B units per thread ----
    uint32_t aoff[4], adst[4], boff[4], bdst[4];
    int asz[4];
#pragma unroll
    for (int t = 0; t < 4; t++) {
        int u = tid + t * 256;
        int row = u >> 3, q = u & 7;
        int ar = s_map[row];
        asz[t]  = ar >= 0 ? 16 : 0;
        aoff[t] = (uint32_t)((ar < 0 ? 0 : ar) * KDIM * 2 + q * 16);
        adst[t] = sw(row, q);
        int brow = G1 ? (bn0 + (row >> 1) + (row & 1) * F_) : (bn0 + row);
        boff[t] = (uint32_t)(brow * KDIM * 2 + q * 16);
        bdst[t] = PL + sw(row, q);
    }

    auto issue = [&](int b) {   // b = buffer index for the chunk being filled
        const uint32_t base = dynbase + (uint32_t)b * BUF;
#pragma unroll
        for (int t = 0; t < 4; t++) {
            cp_async16(base + adst[t], Ab + aoff[t], asz[t]);
            aoff[t] += 128;
        }
#pragma unroll
        for (int t = 0; t < 4; t++) {
            cp_async16(base + bdst[t], Bb + boff[t], 16);
            boff[t] += 128;
        }
        cp_mbar_arrive(mb0 + b * 8);
    };

    // warp tile: 64 m x 32 n
    const int wm = (wid >> 2) * 64;
    const int wn = (wid & 3) * 32;
    const int lrow  = lane & 15;
    const int qhalf = lane >> 4;

    float acc[4][4][4];
#pragma unroll
    for (int i = 0; i < 4; i++)
#pragma unroll
        for (int j = 0; j < 4; j++)
#pragma unroll
            for (int k = 0; k < 4; k++) acc[i][j][k] = 0.f;

    // prologue: fill all 3 stages (NC >= 3 for both GEMMs)
    issue(0); issue(1); issue(2);

    for (int c = 0; c < NC; c++) {
        const int k3 = c / 3;
        const int b  = c - k3 * 3;
        const uint32_t ph = (uint32_t)(k3 & 1);

        mbar_wait(mb0 + b * 8, ph);     // stage c data + visibility

        const uint32_t base = dynbase + (uint32_t)b * BUF;
        const uint32_t ah = base, bh = base + PL;

#pragma unroll
        for (int kk = 0; kk < 4; kk++) {          // 4 k16 steps per 64-chunk
            const int qlog = kk * 2 + qhalf;
            uint32_t bfh[2][4];
#pragma unroll
            for (int g = 0; g < 2; g++) {
                int r = wn + g * 16 + lrow;
                ldsm4(bfh[g][0], bfh[g][1], bfh[g][2], bfh[g][3], bh + sw(r, qlog));
            }
#pragma unroll
            for (int mi = 0; mi < 4; mi++) {
                int r = wm + mi * 16 + lrow;
                uint32_t afh[4];
                ldsm4(afh[0], afh[1], afh[2], afh[3], ah + sw(r, qlog));
#pragma unroll
                for (int ni = 0; ni < 4; ni++) {
                    const int g = ni >> 1, sub = ni & 1;
                    mma16816(acc[mi][ni], afh, bfh[g][sub], bfh[g][sub + 2]);
                }
            }
        }

        mbar_arrive(me0 + b * 8);       // done consuming stage c
        if (c + 3 < NC) {
            mbar_wait(me0 + b * 8, ph); // all 256 threads done with buffer b
            issue(b);                   // fill buffer b with chunk c+3
        }
    }
    __syncthreads();   // all warps past mainloop; smem reusable for staging

    // ---- epilogue ----
    float* stg = (float*)dynraw;
    const int group = lane >> 2;
    const int tig   = lane & 3;

    if (G1) {
#pragma unroll
        for (int mi = 0; mi < 4; mi++) {
            int m = wm + mi * 16 + group;
#pragma unroll
            for (int ni = 0; ni < 4; ni++) {
                int j = (wid & 3) * 16 + ni * 4 + tig;
                float g0 = acc[mi][ni][0], u0 = acc[mi][ni][1];
                float g1 = acc[mi][ni][2], u1 = acc[mi][ni][3];
                stg[m * 68 + j]       = g0 / (1.f + __expf(-g0)) * u0;
                stg[(m + 8) * 68 + j] = g1 / (1.f + __expf(-g1)) * u1;
            }
        }
        __syncthreads();
#pragma unroll
        for (int t = 0; t < 8; t++) {
            int idx = tid + t * 256;
            int row = idx >> 4, q = idx & 15;
            int orow = s_out[row];
            if (orow >= 0) {
                float4 v = *(const float4*)(stg + row * 68 + q * 4);
                uint32_t h0, h1;
                hi4h(v, h0, h1);
                size_t ob = ((size_t)orow * F_ + bn0 + q * 4) * 2;
                *(uint2*)((char*)g_act_hi + ob) = make_uint2(h0, h1);
            }
        }
    } else {
        // stage C, weighted red.global.add into out[tok] (2 contributions/elem)
#pragma unroll
        for (int mi = 0; mi < 4; mi++) {
            int m = wm + mi * 16 + group;
#pragma unroll
            for (int ni = 0; ni < 4; ni++) {
                int n = wn + ni * 8 + tig * 2;
                *(float2*)(stg + m * 132 + n)       = make_float2(acc[mi][ni][0], acc[mi][ni][1]);
                *(float2*)(stg + (m + 8) * 132 + n) = make_float2(acc[mi][ni][2], acc[mi][ni][3]);
            }
        }
        __syncthreads();
#pragma unroll
        for (int t = 0; t < 16; t++) {
            int idx = tid + t * 256;
            int row = idx >> 5, q = idx & 31;
            int orow = s_out[row];
            if (orow >= 0) {
                float4 v = *(const float4*)(stg + row * 132 + q * 4);
                float w = s_wt[row];
                float* op = outp + (size_t)(orow >> 1) * D_ + bn0 + q * 4;
                redadd(op + 0, w * v.x);
                redadd(op + 1, w * v.y);
                redadd(op + 2, w * v.z);
                redadd(op + 3, w * v.w);
            }
        }
    }
}

// ---------------- launch ----------------
extern "C" void kernel_launch(void* const* d_in, const int* in_sizes, int n_in,
                              void* d_out, int out_size) {
    const float* x   = (const float*)d_in[0];
    const float* gup = (const float*)d_in[1];
    const float* dwn = (const float*)d_in[2];
    const float* tw  = (const float*)d_in[3];
    const int*   ids = (const int*)d_in[4];
    float* out = (float*)d_out;

    cudaFuncSetAttribute(moe_gemm_mma<true>,  cudaFuncAttributeMaxDynamicSharedMemorySize, SMEM_DYN);
    cudaFuncSetAttribute(moe_gemm_mma<false>, cudaFuncAttributeMaxDynamicSharedMemorySize, SMEM_DYN);

    k_route<<<1, 1024>>>(ids);
    k_prep<<<(N4_TOTAL + 255) / 256, 256>>>((const float4*)x, (const float4*)gup,
                                            (const float4*)dwn, (float4*)out);

    moe_gemm_mma<true ><<<dim3(F_ / 64, MAXTILES), 256, SMEM_DYN>>>(tw, out);
    moe_gemm_mma<false><<<dim3(D_ / 128, MAXTILES), 256, SMEM_DYN>>>(tw, out);
}

// round 16
// speedup vs baseline: 1.3125x; 1.3125x over previous
#include <cuda_runtime.h>
#include <cuda_fp16.h>
#include <stdint.h>

// ---------------- problem constants ----------------
namespace {
constexpr int T_  = 4096;
constexpr int D_  = 1024;
constexpr int E_  = 8;
constexpr int F_  = 2816;
constexpr int NP  = T_ * 2;       // 8192 (token,k) pairs
constexpr int N1  = 2 * F_;       // 5632
constexpr int BM  = 128;
constexpr int MAXTILES = 72;

// smem per k64-chunk buffer: 2 planes (Ah, Bh) of 128x64 fp16 = 16KB each
constexpr int PL   = 16384;
constexpr int BUF  = 2 * PL;          // 32768 per buffer
constexpr int NBUF = 3;
constexpr int SMEM_DYN = NBUF * BUF;  // 98304 (>= G2 staging 67584)

// prep region sizes (float4 units)
constexpr int N4_X   = T_ * D_ / 4;
constexpr int N4_GUP = (int)((size_t)E_ * N1 * D_ / 4);
constexpr int N4_DWN = (int)((size_t)E_ * D_ * F_ / 4);
constexpr int N4_OUT = T_ * D_ / 4;
constexpr int N4_TOTAL = N4_X + N4_GUP + N4_DWN + N4_OUT;
}

// ---------------- device scratch ----------------
__device__ __align__(16) __half g_x_hi[(size_t)T_ * D_];
__device__ __align__(16) __half g_gup_hi[(size_t)E_ * N1 * D_];
__device__ __align__(16) __half g_dwn_hi[(size_t)E_ * D_ * F_];
__device__ __align__(16) __half g_act_hi[(size_t)NP * F_];

__device__ int g_rowtok[NP];
__device__ int g_rowpair[NP];
__device__ int g_tile_e[MAXTILES];
__device__ int g_tile_r0[MAXTILES];
__device__ int g_tile_rows[MAXTILES];
__device__ int g_ntiles;

// ---------------- helpers ----------------
__device__ __forceinline__ uint32_t smem_u32(const void* p) {
    uint32_t a;
    asm("{ .reg .u64 t; cvta.to.shared.u64 t, %1; cvt.u32.u64 %0, t; }" : "=r"(a) : "l"(p));
    return a;
}
// SW128 swizzle: tile row r (0..127) = one 128B smem row; 16B unit q (0..7)
__device__ __forceinline__ uint32_t sw(int r, int q) {
    return (uint32_t)((r << 7) | (((q ^ (r & 7))) << 4));
}
__device__ __forceinline__ void hi4h(float4 v, uint32_t& h0, uint32_t& h1) {
    __half2 H0 = __floats2half2_rn(v.x, v.y);
    __half2 H1 = __floats2half2_rn(v.z, v.w);
    h0 = *(uint32_t*)&H0; h1 = *(uint32_t*)&H1;
}
__device__ __forceinline__ void ldsm4(uint32_t& r0, uint32_t& r1, uint32_t& r2, uint32_t& r3,
                                      uint32_t addr) {
    asm volatile("ldmatrix.sync.aligned.m8n8.x4.shared.b16 {%0,%1,%2,%3}, [%4];"
                 : "=r"(r0), "=r"(r1), "=r"(r2), "=r"(r3) : "r"(addr));
}
// non-volatile: register-only op, deps via constraints; ptxas may interleave
__device__ __forceinline__ void mma16816(float* c, const uint32_t* a, uint32_t b0, uint32_t b1) {
    asm("mma.sync.aligned.m16n8k16.row.col.f32.f16.f16.f32 "
        "{%0,%1,%2,%3}, {%4,%5,%6,%7}, {%8,%9}, {%0,%1,%2,%3};"
        : "+f"(c[0]), "+f"(c[1]), "+f"(c[2]), "+f"(c[3])
        : "r"(a[0]), "r"(a[1]), "r"(a[2]), "r"(a[3]), "r"(b0), "r"(b1));
}
__device__ __forceinline__ void cp_async16(uint32_t dst, const void* src, int sz) {
    asm volatile("cp.async.cg.shared.global [%0], [%1], 16, %2;"
                 :: "r"(dst), "l"(src), "r"(sz) : "memory");
}
__device__ __forceinline__ void cp_commit() { asm volatile("cp.async.commit_group;" ::: "memory"); }
__device__ __forceinline__ void cp_wait0()  { asm volatile("cp.async.wait_group 0;" ::: "memory"); }
__device__ __forceinline__ void cp_wait1()  { asm volatile("cp.async.wait_group 1;" ::: "memory"); }
__device__ __forceinline__ void redadd(float* p, float v) {
    asm volatile("red.global.add.f32 [%0], %1;" :: "l"(p), "f"(v) : "memory");
}

// ---------------- merged single-block routing ----------------
__global__ void k_route(const int* __restrict__ ids) {
    __shared__ int scnt[E_];
    __shared__ int soff[E_ + 1];
    const int tid = threadIdx.x;
    if (tid < E_) scnt[tid] = 0;
    __syncthreads();

    int pe[NP / 1024], ps[NP / 1024];
#pragma unroll
    for (int t = 0; t < NP / 1024; t++) {
        int p = tid + t * 1024;
        int e = ids[p];
        e = e < 0 ? 0 : (e >= E_ ? E_ - 1 : e);
        pe[t] = e;
        ps[t] = atomicAdd(&scnt[e], 1);
    }
    __syncthreads();
    if (tid == 0) {
        int off = 0;
        soff[0] = 0;
        for (int e = 0; e < E_; e++) { off += scnt[e]; soff[e + 1] = off; }
        int nt = 0;
        for (int e = 0; e < E_; e++)
            for (int r0 = soff[e]; r0 < soff[e + 1]; r0 += BM) {
                g_tile_e[nt] = e; g_tile_r0[nt] = r0;
                int rem = soff[e + 1] - r0;
                g_tile_rows[nt] = rem < BM ? rem : BM;
                nt++;
            }
        g_ntiles = nt;
    }
    __syncthreads();
#pragma unroll
    for (int t = 0; t < NP / 1024; t++) {
        int p = tid + t * 1024;
        int gr = soff[pe[t]] + ps[t];
        g_rowtok[gr]  = p >> 1;
        g_rowpair[gr] = p;
    }
}

// ---------------- merged prep: fp32 -> fp16 casts + d_out zeroing ----------------
__global__ void k_prep(const float4* __restrict__ x, const float4* __restrict__ gup,
                       const float4* __restrict__ dwn, float4* __restrict__ out) {
    int i = blockIdx.x * 256 + threadIdx.x;
    if (i < N4_X) {
        float4 v = x[i];
        uint32_t h0, h1;
        hi4h(v, h0, h1);
        ((uint2*)g_x_hi)[i] = make_uint2(h0, h1);
        return;
    }
    i -= N4_X;
    if (i < N4_GUP) {
        float4 v = gup[i];
        uint32_t h0, h1;
        hi4h(v, h0, h1);
        ((uint2*)g_gup_hi)[i] = make_uint2(h0, h1);
        return;
    }
    i -= N4_GUP;
    if (i < N4_DWN) {
        float4 v = dwn[i];
        uint32_t h0, h1;
        hi4h(v, h0, h1);
        ((uint2*)g_dwn_hi)[i] = make_uint2(h0, h1);
        return;
    }
    i -= N4_DWN;
    if (i < N4_OUT) out[i] = make_float4(0.f, 0.f, 0.f, 0.f);
}

// ---------------- pure fp16 HMMA grouped GEMM, BK=64, A-frag double-buffer ----
// block 128x128, 8 warps (2m x 4n), warp 64x32, occ 2, 3-stage cp.async,
// SW128 swizzle, one barrier per 64 k, prefetch issued right after barrier.
// Inner loop: A ldsm for mi+1 issued before the 4 mma of mi (latency cover).
// G1: 64 j per block (128 interleaved gate/up B-rows)  KDIM=1024, NC=16
// G2: 128 n per block                                  KDIM=2816, NC=44
template <bool G1>
__global__ void __launch_bounds__(256, 2)
moe_gemm_mma(const float* __restrict__ tw, float* __restrict__ outp) {
    constexpr int KDIM = G1 ? D_ : F_;
    constexpr int NC   = KDIM / 64;

    const int bt = blockIdx.y;
    if (bt >= g_ntiles) return;

    const int e    = g_tile_e[bt];
    const int row0 = g_tile_r0[bt];
    const int rows = g_tile_rows[bt];
    const int bn0  = blockIdx.x * (G1 ? 64 : 128);

    const char* __restrict__ Ab = (const char*)(G1 ? g_x_hi : g_act_hi);
    const size_t eoff = (size_t)e * (G1 ? (size_t)N1 * D_ : (size_t)D_ * F_);
    const char* __restrict__ Bb = (const char*)((G1 ? g_gup_hi : g_dwn_hi) + eoff);

    extern __shared__ __align__(16) char dynraw[];
    const uint32_t dynbase = smem_u32(dynraw);

    __shared__ int   s_map[BM];
    __shared__ int   s_out[BM];
    __shared__ float s_wt[BM];

    const int tid  = threadIdx.x;
    const int wid  = tid >> 5;
    const int lane = tid & 31;

    if (tid < BM) {
        int amap = -1, omap = -1;
        float w = 0.f;
        if (tid < rows) {
            if (G1) { amap = g_rowtok[row0 + tid]; omap = row0 + tid; }
            else    { amap = row0 + tid;           omap = g_rowpair[row0 + tid];
                      w = tw[omap]; }
        }
        s_map[tid] = amap; s_out[tid] = omap; s_wt[tid] = w;
    }
    __syncthreads();

    // ---- hoisted cp.async addressing: 4 A units + 4 B units per thread ----
    uint32_t aoff[4], adst[4], boff[4], bdst[4];
    int asz[4];
#pragma unroll
    for (int t = 0; t < 4; t++) {
        int u = tid + t * 256;
        int row = u >> 3, q = u & 7;
        int ar = s_map[row];
        asz[t]  = ar >= 0 ? 16 : 0;
        aoff[t] = (uint32_t)((ar < 0 ? 0 : ar) * KDIM * 2 + q * 16);
        adst[t] = sw(row, q);
        int brow = G1 ? (bn0 + (row >> 1) + (row & 1) * F_) : (bn0 + row);
        boff[t] = (uint32_t)(brow * KDIM * 2 + q * 16);
        bdst[t] = PL + sw(row, q);
    }

    auto issue = [&](int c) {
        const uint32_t base = dynbase + (uint32_t)(c % NBUF) * BUF;
#pragma unroll
        for (int t = 0; t < 4; t++) {
            cp_async16(base + adst[t], Ab + aoff[t], asz[t]);
            aoff[t] += 128;
        }
#pragma unroll
        for (int t = 0; t < 4; t++) {
            cp_async16(base + bdst[t], Bb + boff[t], 16);
            boff[t] += 128;
        }
        cp_commit();
    };

    // warp tile: 64 m x 32 n
    const int wm = (wid >> 2) * 64;
    const int wn = (wid & 3) * 32;
    const int lrow  = lane & 15;
    const int qhalf = lane >> 4;     // 0/1 -> 16B half within each k32

    float acc[4][4][4];
#pragma unroll
    for (int i = 0; i < 4; i++)
#pragma unroll
        for (int j = 0; j < 4; j++)
#pragma unroll
            for (int k = 0; k < 4; k++) acc[i][j][k] = 0.f;

    issue(0);
    if (NC > 1) issue(1);

    for (int c = 0; c < NC; c++) {
        if (c + 1 < NC) cp_wait1();
        else            cp_wait0();
        __syncthreads();   // stage c visible; all warps done with stage c-1

        // prefetch c+2 immediately: buffer (c+2)%3 == (c-1)%3, released above
        if (c + 2 < NC) issue(c + 2);

        const uint32_t base = dynbase + (uint32_t)(c % NBUF) * BUF;
        const uint32_t ah = base, bh = base + PL;

#pragma unroll
        for (int kk = 0; kk < 4; kk++) {          // 4 k16 steps per 64-chunk
            const int qlog = kk * 2 + qhalf;      // 16B unit 0..7
            uint32_t bfh[2][4];
#pragma unroll
            for (int g = 0; g < 2; g++) {
                int r = wn + g * 16 + lrow;
                ldsm4(bfh[g][0], bfh[g][1], bfh[g][2], bfh[g][3], bh + sw(r, qlog));
            }
            // A-fragment double buffer: ldsm mi+1 issued before mma of mi
            uint32_t af[2][4];
            ldsm4(af[0][0], af[0][1], af[0][2], af[0][3],
                  ah + sw(wm + lrow, qlog));
#pragma unroll
            for (int mi = 0; mi < 4; mi++) {
                const int cur = mi & 1;
                if (mi < 3) {
                    int r = wm + (mi + 1) * 16 + lrow;
                    ldsm4(af[cur ^ 1][0], af[cur ^ 1][1], af[cur ^ 1][2], af[cur ^ 1][3],
                          ah + sw(r, qlog));
                }
#pragma unroll
                for (int ni = 0; ni < 4; ni++) {
                    const int g = ni >> 1, sub = ni & 1;
                    mma16816(acc[mi][ni], af[cur], bfh[g][sub], bfh[g][sub + 2]);
                }
            }
        }
    }
    __syncthreads();

    // ---- epilogue (smem reused for staging) ----
    float* stg = (float*)dynraw;
    const int group = lane >> 2;
    const int tig   = lane & 3;

    if (G1) {
#pragma unroll
        for (int mi = 0; mi < 4; mi++) {
            int m = wm + mi * 16 + group;
#pragma unroll
            for (int ni = 0; ni < 4; ni++) {
                int j = (wid & 3) * 16 + ni * 4 + tig;
                float g0 = acc[mi][ni][0], u0 = acc[mi][ni][1];
                float g1 = acc[mi][ni][2], u1 = acc[mi][ni][3];
                stg[m * 68 + j]       = g0 / (1.f + __expf(-g0)) * u0;
                stg[(m + 8) * 68 + j] = g1 / (1.f + __expf(-g1)) * u1;
            }
        }
        __syncthreads();
#pragma unroll
        for (int t = 0; t < 8; t++) {
            int idx = tid + t * 256;
            int row = idx >> 4, q = idx & 15;
            int orow = s_out[row];
            if (orow >= 0) {
                float4 v = *(const float4*)(stg + row * 68 + q * 4);
                uint32_t h0, h1;
                hi4h(v, h0, h1);
                size_t ob = ((size_t)orow * F_ + bn0 + q * 4) * 2;
                *(uint2*)((char*)g_act_hi + ob) = make_uint2(h0, h1);
            }
        }
    } else {
        // stage C, weighted red.global.add into out[tok] (2 contributions/elem)
#pragma unroll
        for (int mi = 0; mi < 4; mi++) {
            int m = wm + mi * 16 + group;
#pragma unroll
            for (int ni = 0; ni < 4; ni++) {
                int n = wn + ni * 8 + tig * 2;
                *(float2*)(stg + m * 132 + n)       = make_float2(acc[mi][ni][0], acc[mi][ni][1]);
                *(float2*)(stg + (m + 8) * 132 + n) = make_float2(acc[mi][ni][2], acc[mi][ni][3]);
            }
        }
        __syncthreads();
#pragma unroll
        for (int t = 0; t < 16; t++) {
            int idx = tid + t * 256;
            int row = idx >> 5, q = idx & 31;
            int orow = s_out[row];
            if (orow >= 0) {
                float4 v = *(const float4*)(stg + row * 132 + q * 4);
                float w = s_wt[row];
                float* op = outp + (size_t)(orow >> 1) * D_ + bn0 + q * 4;
                redadd(op + 0, w * v.x);
                redadd(op + 1, w * v.y);
                redadd(op + 2, w * v.z);
                redadd(op + 3, w * v.w);
            }
        }
    }
}

// ---------------- launch ----------------
extern "C" void kernel_launch(void* const* d_in, const int* in_sizes, int n_in,
                              void* d_out, int out_size) {
    const float* x   = (const float*)d_in[0];
    const float* gup = (const float*)d_in[1];
    const float* dwn = (const float*)d_in[2];
    const float* tw  = (const float*)d_in[3];
    const int*   ids = (const int*)d_in[4];
    float* out = (float*)d_out;

    cudaFuncSetAttribute(moe_gemm_mma<true>,  cudaFuncAttributeMaxDynamicSharedMemorySize, SMEM_DYN);
    cudaFuncSetAttribute(moe_gemm_mma<false>, cudaFuncAttributeMaxDynamicSharedMemorySize, SMEM_DYN);

    k_route<<<1, 1024>>>(ids);
    k_prep<<<(N4_TOTAL + 255) / 256, 256>>>((const float4*)x, (const float4*)gup,
                                            (const float4*)dwn, (float4*)out);

    moe_gemm_mma<true ><<<dim3(F_ / 64, MAXTILES), 256, SMEM_DYN>>>(tw, out);
    moe_gemm_mma<false><<<dim3(D_ / 128, MAXTILES), 256, SMEM_DYN>>>(tw, out);
}